// round 3
// baseline (speedup 1.0000x reference)
#include <cuda_runtime.h>
#include <cuda_bf16.h>

// PatchShuffle: T=1024 (16 rows x 64 cols), B=64, C=768, STRIPE_W=48.
// Output (flattened fp32, concatenated):
//   visible [256,64,768], fwd [1024,64], bwd [1024,64], stripe_bounds [2,64]
//
// perm (per batch, given start s): argsort of col + 64*in_stripe (distinct keys):
//   i < s          -> i
//   s <= i < 16    -> i + 48
//   16 <= i < 64   -> s + (i - 16)
// inverse (bwd = argsort(fwd) = analytic inverse, fwd is a permutation):
//   c < s          -> c
//   c >= s + 48    -> c - 48
//   else           -> 16 + (c - s)

#define B_ 64
#define C_ 768
#define SW_ 48
#define NVIS_ 256                        // min_visible rows
#define VEC_ (C_ / 4)                    // 192 float4 per row
#define VIS_ELEMS (NVIS_ * B_ * C_)      // 12582912
#define IDX_ELEMS (1024 * B_)            // 65536
#define NBLOCKS (NVIS_ * B_)             // 16384

__device__ __forceinline__ int perm_col(int i, int s) {
    if (i < 16) return (i < s) ? i : (i + SW_);
    return s + (i - 16);
}

__device__ __forceinline__ int inv_col(int c, int s) {
    if (c < s) return c;
    if (c >= s + SW_) return c - SW_;
    return 16 + (c - s);
}

// Fused kernel. One block per visible output row (t,b); 192 threads copy one
// float4 each. Threads 0-3 additionally emit 4 fwd/bwd entries (16384 blocks
// x 4 = 65536 total); thread 4 of the first 128 blocks emits stripe_bounds.
__global__ __launch_bounds__(192, 8)
void ps_fused_kernel(const float4* __restrict__ patches,
                     const int* __restrict__ start_cols,
                     float4* __restrict__ out_vis,
                     float* __restrict__ out_fwd,
                     float* __restrict__ out_bwd,
                     float* __restrict__ out_sb) {
    const int tb  = blockIdx.x;          // [0, 16384)
    const int tid = threadIdx.x;

    // ---- bulk gather: visible[t,b,:] = patches[(t>>6)*64 + perm(t&63), b, :]
    {
        int b   = tb & (B_ - 1);
        int t   = tb >> 6;
        int s   = __ldg(&start_cols[b]);
        int src_t = ((t >> 6) << 6) + perm_col(t & 63, s);
        const float4* src = patches + ((size_t)(src_t * B_ + b)) * VEC_;
        float4*       dst = out_vis + ((size_t)tb) * VEC_;
        dst[tid] = src[tid];
    }

    // ---- index outputs: 4 (fwd, bwd) pairs per block
    if (tid < 4) {
        int i = tb * 4 + tid;            // [0, 65536)
        int b = i & (B_ - 1);
        int t = i >> 6;
        int s = __ldg(&start_cols[b]);
        int row = (t >> 6) << 6;
        int col = t & 63;
        out_fwd[i] = (float)(row + perm_col(col, s));
        out_bwd[i] = (float)(row + inv_col(col, s));
    }

    // ---- stripe_bounds [2,64]: first 128 blocks, thread 4
    if (tid == 4 && tb < 2 * B_) {
        int bb = tb & (B_ - 1);
        int sb = __ldg(&start_cols[bb]);
        out_sb[tb] = (float)((tb < B_) ? sb : (sb + SW_));
    }
}

extern "C" void kernel_launch(void* const* d_in, const int* in_sizes, int n_in,
                              void* d_out, int out_size) {
    const float4* patches    = (const float4*)d_in[0];    // (1024, 64, 768) fp32
    const int*    start_cols = (const int*)d_in[1];       // (64,) int32

    float* out = (float*)d_out;
    float4* out_vis = (float4*)out;                       // 12582912 floats
    float*  out_fwd = out + VIS_ELEMS;                    // 65536
    float*  out_bwd = out_fwd + IDX_ELEMS;                // 65536
    float*  out_sb  = out_bwd + IDX_ELEMS;                // 128

    ps_fused_kernel<<<NBLOCKS, VEC_>>>(patches, start_cols,
                                       out_vis, out_fwd, out_bwd, out_sb);
}

// round 5
// speedup vs baseline: 1.1555x; 1.1555x over previous
#include <cuda_runtime.h>
#include <cuda_bf16.h>

// PatchShuffle: T=1024 (16 rows x 64 cols), B=64, C=768, STRIPE_W=48.
// Output (flattened fp32, concatenated):
//   visible [256,64,768], fwd [1024,64], bwd [1024,64], stripe_bounds [2,64]
//
// perm (per batch, given start s): argsort of col + 64*in_stripe (distinct keys):
//   i < s          -> i
//   s <= i < 16    -> i + 48
//   16 <= i < 64   -> s + (i - 16)
// inverse (bwd = argsort(fwd) = analytic inverse):
//   c < s          -> c
//   c >= s + 48    -> c - 48
//   else           -> 16 + (c - s)

#define B_ 64
#define C_ 768
#define SW_ 48
#define NVIS_ 256                        // min_visible rows
#define VEC_ (C_ / 4)                    // 192 float4 per row
#define VIS_ELEMS (NVIS_ * B_ * C_)      // 12582912
#define IDX_ELEMS (1024 * B_)            // 65536
#define NROWS (NVIS_ * B_)               // 16384 output rows
#define GRID_ (148 * 10)                 // 1480 blocks = exactly 1 wave @ occ 10

__device__ __forceinline__ int perm_col(int i, int s) {
    if (i < 16) return (i < s) ? i : (i + SW_);
    return s + (i - 16);
}

__device__ __forceinline__ int inv_col(int c, int s) {
    if (c < s) return c;
    if (c >= s + SW_) return c - SW_;
    return 16 + (c - s);
}

__device__ __forceinline__ const float4* src_row(const float4* __restrict__ patches,
                                                 const int* __restrict__ sc,
                                                 int tb) {
    int b = tb & (B_ - 1);
    int t = tb >> 6;
    int s = sc[b];
    int src_t = ((t >> 6) << 6) + perm_col(t & 63, s);
    return patches + ((size_t)(src_t * B_ + b)) * VEC_;
}

__device__ __forceinline__ void emit_idx(const int* __restrict__ sc,
                                         float* __restrict__ out_fwd,
                                         float* __restrict__ out_bwd,
                                         int r, int tid) {
    // 4 (fwd,bwd) pairs per row-slot, threads 0-3
    int i = r * 4 + tid;                 // [0, 65536)
    int b = i & (B_ - 1);
    int t = i >> 6;
    int s = sc[b];
    int rowbase = (t >> 6) << 6;
    int col = t & 63;
    out_fwd[i] = (float)(rowbase + perm_col(col, s));
    out_bwd[i] = (float)(rowbase + inv_col(col, s));
}

// Persistent one-wave kernel: 1480 blocks x 192 threads. Each block handles
// rows {blockIdx.x + k*1480}, two rows per iteration with batched loads.
__global__ __launch_bounds__(192, 10)
void ps_fused_kernel(const float4* __restrict__ patches,
                     const int* __restrict__ start_cols,
                     float4* __restrict__ out_vis,
                     float* __restrict__ out_fwd,
                     float* __restrict__ out_bwd,
                     float* __restrict__ out_sb) {
    __shared__ int sc[B_];
    const int tid = threadIdx.x;
    if (tid < B_) sc[tid] = __ldg(&start_cols[tid]);
    __syncthreads();

    // stripe_bounds [2,64]: first 128 blocks, thread 4
    if (tid == 4 && blockIdx.x < 2 * B_) {
        int tb = blockIdx.x;
        int sb = sc[tb & (B_ - 1)];
        out_sb[tb] = (float)((tb < B_) ? sb : (sb + SW_));
    }

    int r = blockIdx.x;
    // paired iterations: rows r and r+GRID_, loads batched for MLP=2
    while (r + GRID_ < NROWS) {
        const float4* s0 = src_row(patches, sc, r);
        const float4* s1 = src_row(patches, sc, r + GRID_);
        float4 v0 = s0[tid];
        float4 v1 = s1[tid];
        out_vis[(size_t)r * VEC_ + tid]           = v0;
        out_vis[(size_t)(r + GRID_) * VEC_ + tid] = v1;
        if (tid < 4) {
            emit_idx(sc, out_fwd, out_bwd, r, tid);
            emit_idx(sc, out_fwd, out_bwd, r + GRID_, tid);
        }
        r += 2 * GRID_;
    }
    // tail row (at most one)
    if (r < NROWS) {
        const float4* s0 = src_row(patches, sc, r);
        out_vis[(size_t)r * VEC_ + tid] = s0[tid];
        if (tid < 4) emit_idx(sc, out_fwd, out_bwd, r, tid);
    }
}

extern "C" void kernel_launch(void* const* d_in, const int* in_sizes, int n_in,
                              void* d_out, int out_size) {
    const float4* patches    = (const float4*)d_in[0];    // (1024, 64, 768) fp32
    const int*    start_cols = (const int*)d_in[1];       // (64,) int32

    float* out = (float*)d_out;
    float4* out_vis = (float4*)out;                       // 12582912 floats
    float*  out_fwd = out + VIS_ELEMS;                    // 65536
    float*  out_bwd = out_fwd + IDX_ELEMS;                // 65536
    float*  out_sb  = out_bwd + IDX_ELEMS;                // 128

    ps_fused_kernel<<<GRID_, VEC_>>>(patches, start_cols,
                                     out_vis, out_fwd, out_bwd, out_sb);
}